// round 2
// baseline (speedup 1.0000x reference)
#include <cuda_runtime.h>
#include <math.h>

// Problem constants (fixed by setup_inputs)
#define Bn   16
#define Cn   67
#define Hn   128
#define Wn   128
#define MAIN 64
#define Gn   8
#define K2n  9
#define Pm   72     // G*K2
#define Pr   9
#define HW   (Hn*Wn)                  // 16384
#define NTOT ((size_t)Bn*Cn*Hn*Wn)    // 17563648
#define EPSc 1e-5f

// Device scratch (no dynamic allocation allowed)
__device__ float g_pooled[Bn * Cn];
__device__ float g_km[Bn * Pm];   // softmaxed main kernels
__device__ float g_kr[Bn * Pr];   // softmaxed remainder kernels

// ---------------------------------------------------------------------------
// Kernel 1: global average pool over H*W for each (b, c)
// grid = B*C blocks, 256 threads
// ---------------------------------------------------------------------------
__global__ void pool_kernel(const float* __restrict__ x) {
    int bc = blockIdx.x;
    const float4* xp = reinterpret_cast<const float4*>(x + (size_t)bc * HW);
    int t = threadIdx.x;

    float s = 0.f;
#pragma unroll
    for (int i = 0; i < 16; ++i) {           // 16 * 256 * 4 = 16384
        float4 v = xp[t + i * 256];
        s += (v.x + v.y) + (v.z + v.w);
    }
#pragma unroll
    for (int off = 16; off > 0; off >>= 1)
        s += __shfl_xor_sync(0xFFFFFFFFu, s, off);

    __shared__ float ws[8];
    if ((t & 31) == 0) ws[t >> 5] = s;
    __syncthreads();
    if (t == 0) {
        float tot = 0.f;
#pragma unroll
        for (int i = 0; i < 8; ++i) tot += ws[i];
        g_pooled[bc] = tot * (1.f / (float)HW);
    }
}

// ---------------------------------------------------------------------------
// Kernel 2: dynamic kernel generation (GEMV + sigmoid gate + BN + softmax)
// grid = B blocks, 128 threads
// ---------------------------------------------------------------------------
__global__ void gen_kernel(const float* __restrict__ w_main,
                           const float* __restrict__ w_gate_main,
                           const float* __restrict__ w_rem,
                           const float* __restrict__ w_gate_rem,
                           const float* __restrict__ gm, const float* __restrict__ bm,
                           const float* __restrict__ mm, const float* __restrict__ vm,
                           const float* __restrict__ gr, const float* __restrict__ br,
                           const float* __restrict__ mr, const float* __restrict__ vr) {
    int b = blockIdx.x;
    int t = threadIdx.x;

    __shared__ float pooled_s[Cn];
    __shared__ float km_raw[Pm];
    __shared__ float km_bn[Pm];
    __shared__ float kr_raw[Pr];
    __shared__ float kr_bn[Pr];

    if (t < Cn) pooled_s[t] = g_pooled[b * Cn + t];
    __syncthreads();

    if (t < Pm) {
        float s = 0.f;
#pragma unroll 1
        for (int c = 0; c < Cn; ++c) s += pooled_s[c] * w_main[t * Cn + c];
        km_raw[t] = s;
    }
    if (t >= Pm && t < Pm + Pr) {
        int p = t - Pm;
        float s = 0.f;
        for (int c = 0; c < Cn; ++c) s += pooled_s[c] * w_rem[p * Cn + c];
        kr_raw[p] = s;
    }
    __syncthreads();

    if (t < Pm) {
        float g = 0.f;
#pragma unroll 1
        for (int p = 0; p < Pm; ++p) g += km_raw[p] * w_gate_main[t * Pm + p];
        float v = km_raw[t] * (1.f / (1.f + expf(-g)));
        v = gm[t] * (v - mm[t]) * rsqrtf(vm[t] + EPSc) + bm[t];
        km_bn[t] = v;
    }
    if (t >= Pm && t < Pm + Pr) {
        int q = t - Pm;
        float g = 0.f;
        for (int p = 0; p < Pr; ++p) g += kr_raw[p] * w_gate_rem[q * Pr + p];
        float v = kr_raw[q] * (1.f / (1.f + expf(-g)));
        v = gr[q] * (v - mr[q]) * rsqrtf(vr[q] + EPSc) + br[q];
        kr_bn[q] = v;
    }
    __syncthreads();

    // softmax: threads 0..7 handle main groups; thread 8 handles remainder
    if (t < Gn) {
        float mx = -1e30f;
#pragma unroll
        for (int k = 0; k < K2n; ++k) mx = fmaxf(mx, km_bn[t * K2n + k]);
        float e[K2n]; float s = 0.f;
#pragma unroll
        for (int k = 0; k < K2n; ++k) { e[k] = expf(km_bn[t * K2n + k] - mx); s += e[k]; }
        float inv = 1.f / s;
#pragma unroll
        for (int k = 0; k < K2n; ++k) g_km[b * Pm + t * K2n + k] = e[k] * inv;
    } else if (t == Gn) {
        float mx = -1e30f;
#pragma unroll
        for (int k = 0; k < K2n; ++k) mx = fmaxf(mx, kr_bn[k]);
        float e[K2n]; float s = 0.f;
#pragma unroll
        for (int k = 0; k < K2n; ++k) { e[k] = expf(kr_bn[k] - mx); s += e[k]; }
        float inv = 1.f / s;
#pragma unroll
        for (int k = 0; k < K2n; ++k) g_kr[b * Pr + k] = e[k] * inv;
    }
}

// ---------------------------------------------------------------------------
// Kernel 3: reflect-padded 3x3 dynamic conv + residual, vectorized x4.
// grid = (H/8, C, B); block = (32, 8) = 256 threads.
// Each thread computes 4 contiguous output pixels; stores via STG.128.
// ---------------------------------------------------------------------------
#define TILE_H 8
__global__ void __launch_bounds__(256, 6)
conv_kernel(const float* __restrict__ x, float* __restrict__ out) {
    int b  = blockIdx.z;
    int c  = blockIdx.y;
    int h0 = blockIdx.x * TILE_H;

    // tile[r][col], col 0..129 maps to gw = col-1 (reflect at edges)
    __shared__ float tile[TILE_H + 2][132];
    __shared__ float wks[K2n];

    int tx  = threadIdx.x;            // 0..31
    int ty  = threadIdx.y;            // 0..7
    int lin = ty * 32 + tx;           // 0..255

    if (lin < K2n) {
        wks[lin] = (c < MAIN) ? g_km[b * Pm + (c >> 3) * K2n + lin]
                              : g_kr[b * Pr + lin];
    }

    const float* xc = x + ((size_t)(b * Cn + c)) * HW;

    // --- halo load: interior 128 cols per row via float4, edges scalar ---
    // 10 rows * 32 float4 = 320 vec loads over 256 threads
    for (int i = lin; i < (TILE_H + 2) * 32; i += 256) {
        int r  = i >> 5;              // 0..9
        int v  = i & 31;              // 0..31  -> cols 4v..4v+3
        int gh = h0 + r - 1;
        gh = (gh < 0) ? 1 : ((gh > Hn - 1) ? Hn - 2 : gh);
        float4 val = *reinterpret_cast<const float4*>(xc + gh * Wn + v * 4);
        tile[r][1 + v * 4 + 0] = val.x;
        tile[r][1 + v * 4 + 1] = val.y;
        tile[r][1 + v * 4 + 2] = val.z;
        tile[r][1 + v * 4 + 3] = val.w;
    }
    // edge columns: col 0 -> gw=-1 reflects to 1; col 129 -> gw=128 reflects to 126
    if (lin < (TILE_H + 2) * 2) {
        int r    = lin >> 1;
        int side = lin & 1;
        int gh = h0 + r - 1;
        gh = (gh < 0) ? 1 : ((gh > Hn - 1) ? Hn - 2 : gh);
        if (side == 0) tile[r][0]   = xc[gh * Wn + 1];
        else           tile[r][129] = xc[gh * Wn + 126];
    }
    __syncthreads();

    float w0 = wks[0], w1 = wks[1], w2 = wks[2];
    float w3 = wks[3], w4 = wks[4], w5 = wks[5];
    float w6 = wks[6], w7 = wks[7], w8 = wks[8];

    int col0 = tx * 4;   // output cols col0..col0+3; tile col index = col0..col0+5

    // register-shift across the 3 rows: load 6 values per row, produce 4 outputs
    float r0a = tile[ty    ][col0], r0b = tile[ty    ][col0+1], r0c = tile[ty    ][col0+2],
          r0d = tile[ty    ][col0+3], r0e = tile[ty    ][col0+4], r0f = tile[ty    ][col0+5];
    float r1a = tile[ty + 1][col0], r1b = tile[ty + 1][col0+1], r1c = tile[ty + 1][col0+2],
          r1d = tile[ty + 1][col0+3], r1e = tile[ty + 1][col0+4], r1f = tile[ty + 1][col0+5];
    float r2a = tile[ty + 2][col0], r2b = tile[ty + 2][col0+1], r2c = tile[ty + 2][col0+2],
          r2d = tile[ty + 2][col0+3], r2e = tile[ty + 2][col0+4], r2f = tile[ty + 2][col0+5];

    float4 acc, ctr;
    acc.x = w0*r0a + w1*r0b + w2*r0c + w3*r1a + w4*r1b + w5*r1c + w6*r2a + w7*r2b + w8*r2c;
    acc.y = w0*r0b + w1*r0c + w2*r0d + w3*r1b + w4*r1c + w5*r1d + w6*r2b + w7*r2c + w8*r2d;
    acc.z = w0*r0c + w1*r0d + w2*r0e + w3*r1c + w4*r1d + w5*r1e + w6*r2c + w7*r2d + w8*r2e;
    acc.w = w0*r0d + w1*r0e + w2*r0f + w3*r1d + w4*r1e + w5*r1f + w6*r2d + w7*r2e + w8*r2f;

    ctr.x = r1b; ctr.y = r1c; ctr.z = r1d; ctr.w = r1e;

    float4 high;
    high.x = ctr.x - acc.x;
    high.y = ctr.y - acc.y;
    high.z = ctr.z - acc.z;
    high.w = ctr.w - acc.w;

    int h = h0 + ty;
    size_t oidx = ((size_t)(b * Cn + c) * Hn + h) * Wn + col0;
    *reinterpret_cast<float4*>(out + oidx)        = acc;
    *reinterpret_cast<float4*>(out + NTOT + oidx) = high;
}

// ---------------------------------------------------------------------------
extern "C" void kernel_launch(void* const* d_in, const int* in_sizes, int n_in,
                              void* d_out, int out_size) {
    const float* x           = (const float*)d_in[0];
    const float* w_main      = (const float*)d_in[1];
    const float* w_gate_main = (const float*)d_in[2];
    const float* w_rem       = (const float*)d_in[3];
    const float* w_gate_rem  = (const float*)d_in[4];
    const float* gm = (const float*)d_in[5];
    const float* bm = (const float*)d_in[6];
    const float* mm = (const float*)d_in[7];
    const float* vm = (const float*)d_in[8];
    const float* gr = (const float*)d_in[9];
    const float* br = (const float*)d_in[10];
    const float* mr = (const float*)d_in[11];
    const float* vr = (const float*)d_in[12];
    float* out = (float*)d_out;

    pool_kernel<<<Bn * Cn, 256>>>(x);
    gen_kernel<<<Bn, 128>>>(w_main, w_gate_main, w_rem, w_gate_rem,
                            gm, bm, mm, vm, gr, br, mr, vr);
    dim3 grid(Hn / TILE_H, Cn, Bn);
    dim3 block(32, TILE_H);
    conv_kernel<<<grid, block>>>(x, out);
}

// round 7
// speedup vs baseline: 1.6995x; 1.6995x over previous
#include <cuda_runtime.h>
#include <math.h>

// Problem constants (fixed by setup_inputs)
#define Bn   16
#define Cn   67
#define Hn   128
#define Wn   128
#define MAIN 64
#define Gn   8
#define K2n  9
#define Pm   72     // G*K2
#define Pr   9
#define HW   (Hn*Wn)                  // 16384
#define NTOT ((size_t)Bn*Cn*Hn*Wn)    // 17563648
#define EPSc 1e-5f

// Device scratch (no dynamic allocation allowed)
__device__ float g_pooled[Bn * Cn];
__device__ float g_km[Bn * Pm];   // softmaxed main kernels
__device__ float g_kr[Bn * Pr];   // softmaxed remainder kernels

// ---------------------------------------------------------------------------
// Kernel 1: global average pool over H*W for each (b, c)
// grid = B*C blocks, 256 threads. Default-cached loads warm L2 with x.
// ---------------------------------------------------------------------------
__global__ void pool_kernel(const float* __restrict__ x) {
    int bc = blockIdx.x;
    const float4* xp = reinterpret_cast<const float4*>(x + (size_t)bc * HW);
    int t = threadIdx.x;

    float s = 0.f;
#pragma unroll
    for (int i = 0; i < 16; ++i) {           // 16 * 256 * 4 = 16384
        float4 v = xp[t + i * 256];
        s += (v.x + v.y) + (v.z + v.w);
    }
#pragma unroll
    for (int off = 16; off > 0; off >>= 1)
        s += __shfl_xor_sync(0xFFFFFFFFu, s, off);

    __shared__ float ws[8];
    if ((t & 31) == 0) ws[t >> 5] = s;
    __syncthreads();
    if (t == 0) {
        float tot = 0.f;
#pragma unroll
        for (int i = 0; i < 8; ++i) tot += ws[i];
        g_pooled[bc] = tot * (1.f / (float)HW);
    }
}

// ---------------------------------------------------------------------------
// Kernel 2: dynamic kernel generation (GEMV + sigmoid gate + BN + softmax)
// grid = B blocks, 128 threads
// ---------------------------------------------------------------------------
__global__ void gen_kernel(const float* __restrict__ w_main,
                           const float* __restrict__ w_gate_main,
                           const float* __restrict__ w_rem,
                           const float* __restrict__ w_gate_rem,
                           const float* __restrict__ gm, const float* __restrict__ bm,
                           const float* __restrict__ mm, const float* __restrict__ vm,
                           const float* __restrict__ gr, const float* __restrict__ br,
                           const float* __restrict__ mr, const float* __restrict__ vr) {
    int b = blockIdx.x;
    int t = threadIdx.x;

    __shared__ float pooled_s[Cn];
    __shared__ float km_raw[Pm];
    __shared__ float km_bn[Pm];
    __shared__ float kr_raw[Pr];
    __shared__ float kr_bn[Pr];

    if (t < Cn) pooled_s[t] = g_pooled[b * Cn + t];
    __syncthreads();

    if (t < Pm) {
        float s = 0.f;
        for (int c = 0; c < Cn; ++c) s += pooled_s[c] * w_main[t * Cn + c];
        km_raw[t] = s;
    }
    if (t >= Pm && t < Pm + Pr) {
        int p = t - Pm;
        float s = 0.f;
        for (int c = 0; c < Cn; ++c) s += pooled_s[c] * w_rem[p * Cn + c];
        kr_raw[p] = s;
    }
    __syncthreads();

    if (t < Pm) {
        float g = 0.f;
        for (int p = 0; p < Pm; ++p) g += km_raw[p] * w_gate_main[t * Pm + p];
        float v = km_raw[t] * (1.f / (1.f + expf(-g)));
        v = gm[t] * (v - mm[t]) * rsqrtf(vm[t] + EPSc) + bm[t];
        km_bn[t] = v;
    }
    if (t >= Pm && t < Pm + Pr) {
        int q = t - Pm;
        float g = 0.f;
        for (int p = 0; p < Pr; ++p) g += kr_raw[p] * w_gate_rem[q * Pr + p];
        float v = kr_raw[q] * (1.f / (1.f + expf(-g)));
        v = gr[q] * (v - mr[q]) * rsqrtf(vr[q] + EPSc) + br[q];
        kr_bn[q] = v;
    }
    __syncthreads();

    // softmax: threads 0..7 handle main groups; thread 8 handles remainder
    if (t < Gn) {
        float mx = -1e30f;
#pragma unroll
        for (int k = 0; k < K2n; ++k) mx = fmaxf(mx, km_bn[t * K2n + k]);
        float e[K2n]; float s = 0.f;
#pragma unroll
        for (int k = 0; k < K2n; ++k) { e[k] = expf(km_bn[t * K2n + k] - mx); s += e[k]; }
        float inv = 1.f / s;
#pragma unroll
        for (int k = 0; k < K2n; ++k) g_km[b * Pm + t * K2n + k] = e[k] * inv;
    } else if (t == Gn) {
        float mx = -1e30f;
#pragma unroll
        for (int k = 0; k < K2n; ++k) mx = fmaxf(mx, kr_bn[k]);
        float e[K2n]; float s = 0.f;
#pragma unroll
        for (int k = 0; k < K2n; ++k) { e[k] = expf(kr_bn[k] - mx); s += e[k]; }
        float inv = 1.f / s;
#pragma unroll
        for (int k = 0; k < K2n; ++k) g_kr[b * Pr + k] = e[k] * inv;
    }
}

// ---------------------------------------------------------------------------
// Kernel 3: reflect-padded 3x3 dynamic conv + residual.
// NO shared memory: each thread computes a 4-wide x 4-row micro-tile from
// 6x LDG.128 (rows reused across outputs), column neighbors via warp
// shuffle, reflect via row-index clamp and lane-edge overrides.
// Streaming stores (__stcs) keep the 140MB write stream from evicting x
// out of L2.
// grid = (H/16, C, B); block = (32, 4) = 128 threads.
// ---------------------------------------------------------------------------
__device__ __forceinline__ void row_acc(float4& acc, const float4& v, float l, float r,
                                        float wa, float wb, float wc) {
    acc.x += wa * l   + wb * v.x + wc * v.y;
    acc.y += wa * v.x + wb * v.y + wc * v.z;
    acc.z += wa * v.y + wb * v.z + wc * v.w;
    acc.w += wa * v.z + wb * v.w + wc * r;
}

__global__ void __launch_bounds__(128)
conv_kernel(const float* __restrict__ x, float* __restrict__ out) {
    int b  = blockIdx.z;
    int c  = blockIdx.y;
    int tx = threadIdx.x;                   // 0..31
    int ty = threadIdx.y;                   // 0..3
    int h0 = blockIdx.x * 16 + ty * 4;      // first of 4 output rows
    int col0 = tx * 4;

    // broadcast weight load (uniform address per block)
    const float* wp = (c < MAIN) ? &g_km[b * Pm + (c >> 3) * K2n]
                                 : &g_kr[b * Pr];
    float w0 = wp[0], w1 = wp[1], w2 = wp[2];
    float w3 = wp[3], w4 = wp[4], w5 = wp[5];
    float w6 = wp[6], w7 = wp[7], w8 = wp[8];

    const float* xc = x + ((size_t)(b * Cn + c)) * HW;

    // input rows h0-1 .. h0+4, reflect-clamped at image edges
    float4 r[6];
    float  ln[6], rn[6];
#pragma unroll
    for (int i = 0; i < 6; ++i) {
        int gh = h0 - 1 + i;
        gh = (gh < 0) ? 1 : ((gh > Hn - 1) ? Hn - 2 : gh);
        r[i] = *reinterpret_cast<const float4*>(xc + gh * Wn + col0);
    }
#pragma unroll
    for (int i = 0; i < 6; ++i) {
        float l  = __shfl_up_sync(0xFFFFFFFFu, r[i].w, 1);
        float rr = __shfl_down_sync(0xFFFFFFFFu, r[i].x, 1);
        if (tx == 0)  l  = r[i].y;   // col -1  reflects to col 1
        if (tx == 31) rr = r[i].z;   // col 128 reflects to col 126
        ln[i] = l; rn[i] = rr;
    }

    size_t obase = ((size_t)(b * Cn + c) * Hn + h0) * Wn + col0;

#pragma unroll
    for (int j = 0; j < 4; ++j) {
        float4 acc = make_float4(0.f, 0.f, 0.f, 0.f);
        row_acc(acc, r[j    ], ln[j    ], rn[j    ], w0, w1, w2);
        row_acc(acc, r[j + 1], ln[j + 1], rn[j + 1], w3, w4, w5);
        row_acc(acc, r[j + 2], ln[j + 2], rn[j + 2], w6, w7, w8);

        float4 high = make_float4(r[j + 1].x - acc.x, r[j + 1].y - acc.y,
                                  r[j + 1].z - acc.z, r[j + 1].w - acc.w);

        __stcs(reinterpret_cast<float4*>(out + obase + (size_t)j * Wn), acc);
        __stcs(reinterpret_cast<float4*>(out + NTOT + obase + (size_t)j * Wn), high);
    }
}

// ---------------------------------------------------------------------------
extern "C" void kernel_launch(void* const* d_in, const int* in_sizes, int n_in,
                              void* d_out, int out_size) {
    const float* x           = (const float*)d_in[0];
    const float* w_main      = (const float*)d_in[1];
    const float* w_gate_main = (const float*)d_in[2];
    const float* w_rem       = (const float*)d_in[3];
    const float* w_gate_rem  = (const float*)d_in[4];
    const float* gm = (const float*)d_in[5];
    const float* bm = (const float*)d_in[6];
    const float* mm = (const float*)d_in[7];
    const float* vm = (const float*)d_in[8];
    const float* gr = (const float*)d_in[9];
    const float* br = (const float*)d_in[10];
    const float* mr = (const float*)d_in[11];
    const float* vr = (const float*)d_in[12];
    float* out = (float*)d_out;

    pool_kernel<<<Bn * Cn, 256>>>(x);
    gen_kernel<<<Bn, 128>>>(w_main, w_gate_main, w_rem, w_gate_rem,
                            gm, bm, mm, vm, gr, br, mr, vr);
    dim3 grid(Hn / 16, Cn, Bn);
    dim3 block(32, 4);
    conv_kernel<<<grid, block>>>(x, out);
}

// round 11
// speedup vs baseline: 1.7175x; 1.0106x over previous
#include <cuda_runtime.h>
#include <math.h>

// Problem constants (fixed by setup_inputs)
#define Bn   16
#define Cn   67
#define Hn   128
#define Wn   128
#define MAIN 64
#define Gn   8
#define K2n  9
#define Pm   72     // G*K2
#define Pr   9
#define HW   (Hn*Wn)                  // 16384
#define NTOT ((size_t)Bn*Cn*Hn*Wn)    // 17563648
#define EPSc 1e-5f

// Device scratch (no dynamic allocation allowed)
__device__ float g_pooled[Bn * Cn];
__device__ float g_km[Bn * Pm];   // softmaxed main kernels
__device__ float g_kr[Bn * Pr];   // softmaxed remainder kernels

// ---------------------------------------------------------------------------
// Kernel 1: global average pool over H*W for each (b, c)
// grid = B*C blocks, 256 threads. Default-cached loads warm L2 with x.
// ---------------------------------------------------------------------------
__global__ void pool_kernel(const float* __restrict__ x) {
    int bc = blockIdx.x;
    const float4* xp = reinterpret_cast<const float4*>(x + (size_t)bc * HW);
    int t = threadIdx.x;

    float s = 0.f;
#pragma unroll
    for (int i = 0; i < 16; ++i) {           // 16 * 256 * 4 = 16384
        float4 v = xp[t + i * 256];
        s += (v.x + v.y) + (v.z + v.w);
    }
#pragma unroll
    for (int off = 16; off > 0; off >>= 1)
        s += __shfl_xor_sync(0xFFFFFFFFu, s, off);

    __shared__ float ws[8];
    if ((t & 31) == 0) ws[t >> 5] = s;
    __syncthreads();
    if (t == 0) {
        float tot = 0.f;
#pragma unroll
        for (int i = 0; i < 8; ++i) tot += ws[i];
        g_pooled[bc] = tot * (1.f / (float)HW);
    }
}

// ---------------------------------------------------------------------------
// Kernel 2: dynamic kernel generation (GEMV + sigmoid gate + BN + softmax)
// grid = B blocks, 128 threads
// ---------------------------------------------------------------------------
__global__ void gen_kernel(const float* __restrict__ w_main,
                           const float* __restrict__ w_gate_main,
                           const float* __restrict__ w_rem,
                           const float* __restrict__ w_gate_rem,
                           const float* __restrict__ gm, const float* __restrict__ bm,
                           const float* __restrict__ mm, const float* __restrict__ vm,
                           const float* __restrict__ gr, const float* __restrict__ br,
                           const float* __restrict__ mr, const float* __restrict__ vr) {
    int b = blockIdx.x;
    int t = threadIdx.x;

    __shared__ float pooled_s[Cn];
    __shared__ float km_raw[Pm];
    __shared__ float km_bn[Pm];
    __shared__ float kr_raw[Pr];
    __shared__ float kr_bn[Pr];

    if (t < Cn) pooled_s[t] = g_pooled[b * Cn + t];
    __syncthreads();

    if (t < Pm) {
        float s = 0.f;
        for (int c = 0; c < Cn; ++c) s += pooled_s[c] * w_main[t * Cn + c];
        km_raw[t] = s;
    }
    if (t >= Pm && t < Pm + Pr) {
        int p = t - Pm;
        float s = 0.f;
        for (int c = 0; c < Cn; ++c) s += pooled_s[c] * w_rem[p * Cn + c];
        kr_raw[p] = s;
    }
    __syncthreads();

    if (t < Pm) {
        float g = 0.f;
        for (int p = 0; p < Pm; ++p) g += km_raw[p] * w_gate_main[t * Pm + p];
        float v = km_raw[t] * (1.f / (1.f + expf(-g)));
        v = gm[t] * (v - mm[t]) * rsqrtf(vm[t] + EPSc) + bm[t];
        km_bn[t] = v;
    }
    if (t >= Pm && t < Pm + Pr) {
        int q = t - Pm;
        float g = 0.f;
        for (int p = 0; p < Pr; ++p) g += kr_raw[p] * w_gate_rem[q * Pr + p];
        float v = kr_raw[q] * (1.f / (1.f + expf(-g)));
        v = gr[q] * (v - mr[q]) * rsqrtf(vr[q] + EPSc) + br[q];
        kr_bn[q] = v;
    }
    __syncthreads();

    // softmax: threads 0..7 handle main groups; thread 8 handles remainder
    if (t < Gn) {
        float mx = -1e30f;
#pragma unroll
        for (int k = 0; k < K2n; ++k) mx = fmaxf(mx, km_bn[t * K2n + k]);
        float e[K2n]; float s = 0.f;
#pragma unroll
        for (int k = 0; k < K2n; ++k) { e[k] = expf(km_bn[t * K2n + k] - mx); s += e[k]; }
        float inv = 1.f / s;
#pragma unroll
        for (int k = 0; k < K2n; ++k) g_km[b * Pm + t * K2n + k] = e[k] * inv;
    } else if (t == Gn) {
        float mx = -1e30f;
#pragma unroll
        for (int k = 0; k < K2n; ++k) mx = fmaxf(mx, kr_bn[k]);
        float e[K2n]; float s = 0.f;
#pragma unroll
        for (int k = 0; k < K2n; ++k) { e[k] = expf(kr_bn[k] - mx); s += e[k]; }
        float inv = 1.f / s;
#pragma unroll
        for (int k = 0; k < K2n; ++k) g_kr[b * Pr + k] = e[k] * inv;
    }
}

// ---------------------------------------------------------------------------
// Kernel 3: reflect-padded 3x3 dynamic conv + residual.
// NO shared memory: each thread computes a 4-wide x 8-row micro-tile from
// 10x LDG.128 (rows reused across outputs: 1.25 row-loads/output-row),
// column neighbors via warp shuffle, reflect via row clamp + lane-edge
// overrides. Streaming stores (__stcs) protect x's L2 residency.
// grid = (H/32, C, B); block = (32, 4) = 128 threads.
// ---------------------------------------------------------------------------
__device__ __forceinline__ void row_acc(float4& acc, const float4& v, float l, float r,
                                        float wa, float wb, float wc) {
    acc.x += wa * l   + wb * v.x + wc * v.y;
    acc.y += wa * v.x + wb * v.y + wc * v.z;
    acc.z += wa * v.y + wb * v.z + wc * v.w;
    acc.w += wa * v.z + wb * v.w + wc * r;
}

__global__ void __launch_bounds__(128)
conv_kernel(const float* __restrict__ x, float* __restrict__ out) {
    int b  = blockIdx.z;
    int c  = blockIdx.y;
    int tx = threadIdx.x;                   // 0..31
    int ty = threadIdx.y;                   // 0..3
    int h0 = blockIdx.x * 32 + ty * 8;      // first of 8 output rows
    int col0 = tx * 4;

    // broadcast weight load (uniform address per block)
    const float* wp = (c < MAIN) ? &g_km[b * Pm + (c >> 3) * K2n]
                                 : &g_kr[b * Pr];
    float w0 = wp[0], w1 = wp[1], w2 = wp[2];
    float w3 = wp[3], w4 = wp[4], w5 = wp[5];
    float w6 = wp[6], w7 = wp[7], w8 = wp[8];

    const float* xc = x + ((size_t)(b * Cn + c)) * HW;

    // input rows h0-1 .. h0+8, reflect-clamped at image edges
    float4 r[10];
    float  ln[10], rn[10];
#pragma unroll
    for (int i = 0; i < 10; ++i) {
        int gh = h0 - 1 + i;
        gh = (gh < 0) ? 1 : ((gh > Hn - 1) ? Hn - 2 : gh);
        r[i] = *reinterpret_cast<const float4*>(xc + gh * Wn + col0);
    }
#pragma unroll
    for (int i = 0; i < 10; ++i) {
        float l  = __shfl_up_sync(0xFFFFFFFFu, r[i].w, 1);
        float rr = __shfl_down_sync(0xFFFFFFFFu, r[i].x, 1);
        if (tx == 0)  l  = r[i].y;   // col -1  reflects to col 1
        if (tx == 31) rr = r[i].z;   // col 128 reflects to col 126
        ln[i] = l; rn[i] = rr;
    }

    size_t obase = ((size_t)(b * Cn + c) * Hn + h0) * Wn + col0;

#pragma unroll
    for (int j = 0; j < 8; ++j) {
        float4 acc = make_float4(0.f, 0.f, 0.f, 0.f);
        row_acc(acc, r[j    ], ln[j    ], rn[j    ], w0, w1, w2);
        row_acc(acc, r[j + 1], ln[j + 1], rn[j + 1], w3, w4, w5);
        row_acc(acc, r[j + 2], ln[j + 2], rn[j + 2], w6, w7, w8);

        float4 high = make_float4(r[j + 1].x - acc.x, r[j + 1].y - acc.y,
                                  r[j + 1].z - acc.z, r[j + 1].w - acc.w);

        __stcs(reinterpret_cast<float4*>(out + obase + (size_t)j * Wn), acc);
        __stcs(reinterpret_cast<float4*>(out + NTOT + obase + (size_t)j * Wn), high);
    }
}

// ---------------------------------------------------------------------------
extern "C" void kernel_launch(void* const* d_in, const int* in_sizes, int n_in,
                              void* d_out, int out_size) {
    const float* x           = (const float*)d_in[0];
    const float* w_main      = (const float*)d_in[1];
    const float* w_gate_main = (const float*)d_in[2];
    const float* w_rem       = (const float*)d_in[3];
    const float* w_gate_rem  = (const float*)d_in[4];
    const float* gm = (const float*)d_in[5];
    const float* bm = (const float*)d_in[6];
    const float* mm = (const float*)d_in[7];
    const float* vm = (const float*)d_in[8];
    const float* gr = (const float*)d_in[9];
    const float* br = (const float*)d_in[10];
    const float* mr = (const float*)d_in[11];
    const float* vr = (const float*)d_in[12];
    float* out = (float*)d_out;

    pool_kernel<<<Bn * Cn, 256>>>(x);
    gen_kernel<<<Bn, 128>>>(w_main, w_gate_main, w_rem, w_gate_rem,
                            gm, bm, mm, vm, gr, br, mr, vr);
    dim3 grid(Hn / 32, Cn, Bn);
    dim3 block(32, 4);
    conv_kernel<<<grid, block>>>(x, out);
}